// round 2
// baseline (speedup 1.0000x reference)
#include <cuda_runtime.h>
#include <cstdint>
#include <math.h>

// ----------------------------------------------------------------------------
// StackDevConv: two DevConv layers.
//   per edge e: x_i = x[dst[e]], x_j = x[src[e]]
//   tmp = [x_i, x_j - x_i]  (1x128)
//   msg = ReLU(tmp @ W1^T + b1) @ W2^T + b2   (1x64)
//   out[n] = segment_max over edges with dst==n ; empty segments -> 0
// NOTE: edge_index is int32 (JAX x64 disabled coerces int64 -> int32).
// ----------------------------------------------------------------------------

#define DIMV   64
#define E_TILE 64
#define TPB    256
#define PAD    68          // padded row stride (floats) for staging arrays

#define MAX_NODES 50000
__device__ float g_h1[MAX_NODES * DIMV];   // layer-1 output scratch

// smem layout (floats):
//   sW1T  [128][PAD]   8704
//   sW2T  [ 64][PAD]   4352
//   sB1   [64]           64
//   sB2   [64]           64
//   sTmpT [128][PAD]   8704   (rows 0..63 reused as sHT after GEMM1)
//   sDst  [64] (int)     64
#define SMEM_FLOATS (128*PAD + 64*PAD + 64 + 64 + 128*PAD + 64)
#define SMEM_BYTES  (SMEM_FLOATS * 4)

__device__ __forceinline__ void atomic_max_float(float* addr, float value) {
    unsigned int ui = __float_as_uint(value);
    if ((int)ui >= 0) {
        atomicMax((int*)addr, (int)ui);            // non-negative floats: int order
    } else {
        atomicMin((unsigned int*)addr, ui);        // negative (incl -0): reversed uint order
    }
}

__global__ void init_neg_inf_kernel(float* p, int n) {
    int i = blockIdx.x * blockDim.x + threadIdx.x;
    if (i < n) ((unsigned int*)p)[i] = 0xFF800000u;   // -inf
}

__global__ void finalize_kernel(float* p, int n) {
    int i = blockIdx.x * blockDim.x + threadIdx.x;
    if (i < n) {
        float v = p[i];
        if (!isfinite(v)) p[i] = 0.0f;
    }
}

__global__ __launch_bounds__(TPB, 2)
void devconv_kernel(const float* __restrict__ x,
                    const int* __restrict__ src,
                    const int* __restrict__ dst,
                    const float* __restrict__ W1, const float* __restrict__ b1,
                    const float* __restrict__ W2, const float* __restrict__ b2,
                    float* __restrict__ out, int n_edges)
{
    extern __shared__ float smem[];
    float* sW1T  = smem;                          // [128][PAD], sW1T[c*PAD+k] = W1[k][c]
    float* sW2T  = sW1T + 128 * PAD;              // [64][PAD]
    float* sB1   = sW2T + 64 * PAD;
    float* sB2   = sB1 + 64;
    float* sTmpT = sB2 + 64;                      // [128][PAD], tmpT[c][e]
    float* sHT   = sTmpT;                         // alias: [64][PAD], hT[k][e]
    int*   sDst  = (int*)(sTmpT + 128 * PAD);

    const int tid = threadIdx.x;

    // ---- stage weights once per (persistent) block ----
    for (int i = tid; i < 64 * 128; i += TPB) {
        int k = i >> 7, c = i & 127;
        sW1T[c * PAD + k] = W1[i];
    }
    for (int i = tid; i < 64 * 64; i += TPB) {
        int k = i >> 6, c = i & 63;
        sW2T[c * PAD + k] = W2[i];
    }
    if (tid < 64) { sB1[tid] = b1[tid]; sB2[tid] = b2[tid]; }
    __syncthreads();

    const int ty = tid >> 4;        // 0..15  -> edge group (rows)
    const int tx = tid & 15;        // 0..15  -> output-col group
    const int r  = ty * 4;
    const int cc = tx * 4;

    const int n_tiles = (n_edges + E_TILE - 1) / E_TILE;

    for (int tile = blockIdx.x; tile < n_tiles; tile += gridDim.x) {
        const int e0 = tile * E_TILE;

        // ---- gather: 4 threads per edge, build tmpT[c][e] ----
        {
            const int e  = tid >> 2;           // 0..63
            const int q  = tid & 3;            // 0..3 (16-float chunk)
            const int eg = e0 + e;
            const bool valid = (eg < n_edges);
            int s = 0, d = 0;
            if (valid) { s = src[eg]; d = dst[eg]; }
            if (q == 0) sDst[e] = valid ? d : -1;
            const float4* xi4 = (const float4*)(x + (size_t)d * DIMV);
            const float4* xj4 = (const float4*)(x + (size_t)s * DIMV);
            #pragma unroll
            for (int v = 0; v < 4; v++) {
                const int c4 = q * 4 + v;      // float4 index 0..15
                float4 a = valid ? xi4[c4] : make_float4(0.f, 0.f, 0.f, 0.f);
                float4 b = valid ? xj4[c4] : make_float4(0.f, 0.f, 0.f, 0.f);
                const int c = c4 * 4;
                sTmpT[(c + 0) * PAD + e] = a.x;
                sTmpT[(c + 1) * PAD + e] = a.y;
                sTmpT[(c + 2) * PAD + e] = a.z;
                sTmpT[(c + 3) * PAD + e] = a.w;
                sTmpT[(64 + c + 0) * PAD + e] = b.x - a.x;
                sTmpT[(64 + c + 1) * PAD + e] = b.y - a.y;
                sTmpT[(64 + c + 2) * PAD + e] = b.z - a.z;
                sTmpT[(64 + c + 3) * PAD + e] = b.w - a.w;
            }
        }
        __syncthreads();

        // ---- GEMM1: H[64e][64k] = tmp @ W1^T ----
        float acc[4][4];
        #pragma unroll
        for (int i = 0; i < 4; i++)
            #pragma unroll
            for (int j = 0; j < 4; j++) acc[i][j] = 0.f;

        #pragma unroll 4
        for (int kc = 0; kc < 128; kc++) {
            const float4 af = *(const float4*)&sTmpT[kc * PAD + r];
            const float4 bf = *(const float4*)&sW1T[kc * PAD + cc];
            const float a0 = af.x, a1 = af.y, a2 = af.z, a3 = af.w;
            acc[0][0] += a0 * bf.x; acc[0][1] += a0 * bf.y; acc[0][2] += a0 * bf.z; acc[0][3] += a0 * bf.w;
            acc[1][0] += a1 * bf.x; acc[1][1] += a1 * bf.y; acc[1][2] += a1 * bf.z; acc[1][3] += a1 * bf.w;
            acc[2][0] += a2 * bf.x; acc[2][1] += a2 * bf.y; acc[2][2] += a2 * bf.z; acc[2][3] += a2 * bf.w;
            acc[3][0] += a3 * bf.x; acc[3][1] += a3 * bf.y; acc[3][2] += a3 * bf.z; acc[3][3] += a3 * bf.w;
        }
        __syncthreads();   // done reading tmpT

        // bias + ReLU, stage hT[k][e] (aliases tmpT rows 0..63)
        #pragma unroll
        for (int i = 0; i < 4; i++)
            #pragma unroll
            for (int j = 0; j < 4; j++) {
                float v = fmaxf(acc[i][j] + sB1[cc + j], 0.f);
                sHT[(cc + j) * PAD + (r + i)] = v;
            }
        __syncthreads();

        // ---- GEMM2: MSG[64e][64m] = H @ W2^T ----
        float acc2[4][4];
        #pragma unroll
        for (int i = 0; i < 4; i++)
            #pragma unroll
            for (int j = 0; j < 4; j++) acc2[i][j] = 0.f;

        #pragma unroll 4
        for (int kc = 0; kc < 64; kc++) {
            const float4 af = *(const float4*)&sHT[kc * PAD + r];
            const float4 bf = *(const float4*)&sW2T[kc * PAD + cc];
            const float a0 = af.x, a1 = af.y, a2 = af.z, a3 = af.w;
            acc2[0][0] += a0 * bf.x; acc2[0][1] += a0 * bf.y; acc2[0][2] += a0 * bf.z; acc2[0][3] += a0 * bf.w;
            acc2[1][0] += a1 * bf.x; acc2[1][1] += a1 * bf.y; acc2[1][2] += a1 * bf.z; acc2[1][3] += a1 * bf.w;
            acc2[2][0] += a2 * bf.x; acc2[2][1] += a2 * bf.y; acc2[2][2] += a2 * bf.z; acc2[2][3] += a2 * bf.w;
            acc2[3][0] += a3 * bf.x; acc2[3][1] += a3 * bf.y; acc2[3][2] += a3 * bf.z; acc2[3][3] += a3 * bf.w;
        }

        // ---- scatter: atomicMax into out[dst] ----
        #pragma unroll
        for (int i = 0; i < 4; i++) {
            const int de = sDst[r + i];
            if (de >= 0) {
                float* op = out + (size_t)de * DIMV + cc;
                #pragma unroll
                for (int j = 0; j < 4; j++) {
                    atomic_max_float(op + j, acc2[i][j] + sB2[cc + j]);
                }
            }
        }
        __syncthreads();   // protect sTmpT/sHT/sDst before next tile's gather
    }
}

extern "C" void kernel_launch(void* const* d_in, const int* in_sizes, int n_in,
                              void* d_out, int out_size)
{
    const float* x   = (const float*)d_in[0];
    const int*   ei  = (const int*)d_in[1];
    const float* W1a = (const float*)d_in[2];
    const float* b1a = (const float*)d_in[3];
    const float* W2a = (const float*)d_in[4];
    const float* b2a = (const float*)d_in[5];
    const float* W1b = (const float*)d_in[6];
    const float* b1b = (const float*)d_in[7];
    const float* W2b = (const float*)d_in[8];
    const float* b2b = (const float*)d_in[9];

    const int n_nodes = in_sizes[0] / DIMV;
    const int n_edges = in_sizes[1] / 2;
    const int* src = ei;
    const int* dst = ei + n_edges;

    float* out = (float*)d_out;
    float* h1  = nullptr;
    cudaGetSymbolAddress((void**)&h1, g_h1);

    cudaFuncSetAttribute(devconv_kernel,
                         cudaFuncAttributeMaxDynamicSharedMemorySize, SMEM_BYTES);

    const int n_feat = n_nodes * DIMV;
    const int init_blocks = (n_feat + TPB - 1) / TPB;
    const int conv_blocks = 296;   // 2 per SM, persistent

    // layer 1: x -> g_h1
    init_neg_inf_kernel<<<init_blocks, TPB>>>(h1, n_feat);
    devconv_kernel<<<conv_blocks, TPB, SMEM_BYTES>>>(x, src, dst,
                                                     W1a, b1a, W2a, b2a,
                                                     h1, n_edges);
    finalize_kernel<<<init_blocks, TPB>>>(h1, n_feat);

    // layer 2: g_h1 -> out
    init_neg_inf_kernel<<<init_blocks, TPB>>>(out, n_feat);
    devconv_kernel<<<conv_blocks, TPB, SMEM_BYTES>>>(h1, src, dst,
                                                     W1b, b1b, W2b, b2b,
                                                     out, n_edges);
    finalize_kernel<<<init_blocks, TPB>>>(out, n_feat);
}

// round 3
// speedup vs baseline: 1.6000x; 1.6000x over previous
#include <cuda_runtime.h>
#include <cstdint>
#include <math.h>

// ----------------------------------------------------------------------------
// StackDevConv, factorized:
//   W1 = [Wa | Wb]  (64 x 128, split along input dim)
//   A[n] = x[n] @ (Wa - Wb)^T + b1      (per node)
//   B[n] = x[n] @ Wb^T                  (per node)
//   per edge: h = ReLU(A[dst] + B[src]);  msg = h @ W2^T + b2
//   out[n]  = max over edges with dst==n ; empty -> 0 (ref maps !finite -> 0)
// edge_index is int32.
// ----------------------------------------------------------------------------

#define DIMV    64
#define TPB     256
#define PADW    68          // weight / x staging stride
#define E_TILE  128
#define PADE    132         // hT e-stride
#define MAX_NODES 50000

__device__ float g_h1[MAX_NODES * DIMV];
__device__ float g_A [MAX_NODES * DIMV];
__device__ float g_B [MAX_NODES * DIMV];

// ---- pre kernel smem: sWdT[64][68] sWbT[64][68] sB1[64] sXT[64][68]
#define PRE_SMEM_FLOATS (64*PADW*3 + 64)
#define PRE_SMEM_BYTES  (PRE_SMEM_FLOATS*4)
// ---- edge kernel smem: sW2T[64][68] sB2[64] sHT[64][132] sDst[128]
#define EDGE_SMEM_FLOATS (64*PADW + 64 + 64*PADE + 128)
#define EDGE_SMEM_BYTES  (EDGE_SMEM_FLOATS*4)

__device__ __forceinline__ void atomic_max_float(float* addr, float value) {
    unsigned int ui = __float_as_uint(value);
    if ((int)ui >= 0) atomicMax((int*)addr, (int)ui);
    else              atomicMin((unsigned int*)addr, ui);
}

__global__ void init_neg_inf_kernel(float* p, int n) {
    int i = blockIdx.x * blockDim.x + threadIdx.x;
    if (i < n) ((unsigned int*)p)[i] = 0xFF800000u;
}

__global__ void finalize_kernel(float* p, int n) {
    int i = blockIdx.x * blockDim.x + threadIdx.x;
    if (i < n) { float v = p[i]; if (!isfinite(v)) p[i] = 0.0f; }
}

// ---------------------------------------------------------------------------
// Per-node precompute: A = x@(Wa-Wb)^T + b1 ; B = x@Wb^T
// One block per 64-node tile. finite_fix: map non-finite x to 0 (fused
// finalize of the previous layer's atomic output).
// ---------------------------------------------------------------------------
__global__ __launch_bounds__(TPB, 3)
void pre_kernel(const float* __restrict__ x,
                const float* __restrict__ W1, const float* __restrict__ b1,
                float* __restrict__ A, float* __restrict__ B,
                int n_nodes, int finite_fix)
{
    extern __shared__ float smem[];
    float* sWdT = smem;                 // [k][c] = Wa[c][k]-Wb[c][k]
    float* sWbT = sWdT + 64 * PADW;     // [k][c] = Wb[c][k]
    float* sB1  = sWbT + 64 * PADW;
    float* sXT  = sB1 + 64;             // [k][n]

    const int tid = threadIdx.x;

    for (int i = tid; i < 64 * 64; i += TPB) {
        int c = i >> 6, k = i & 63;
        float wa = W1[c * 128 + k];
        float wb = W1[c * 128 + 64 + k];
        sWdT[k * PADW + c] = wa - wb;
        sWbT[k * PADW + c] = wb;
    }
    if (tid < 64) sB1[tid] = b1[tid];

    const int n0 = blockIdx.x * 64;
    {
        const int e = tid >> 2;         // local node 0..63
        const int q = tid & 3;          // 4 float4 each
        const int node = n0 + e;
        const float4* xr = (const float4*)(x + (size_t)(node < n_nodes ? node : 0) * DIMV);
        #pragma unroll
        for (int v = 0; v < 4; v++) {
            const int c4 = q * 4 + v;
            float4 a = (node < n_nodes) ? xr[c4] : make_float4(0.f,0.f,0.f,0.f);
            if (finite_fix) {
                if (!isfinite(a.x)) a.x = 0.f;
                if (!isfinite(a.y)) a.y = 0.f;
                if (!isfinite(a.z)) a.z = 0.f;
                if (!isfinite(a.w)) a.w = 0.f;
            }
            const int c = c4 * 4;
            sXT[(c + 0) * PADW + e] = a.x;
            sXT[(c + 1) * PADW + e] = a.y;
            sXT[(c + 2) * PADW + e] = a.z;
            sXT[(c + 3) * PADW + e] = a.w;
        }
    }
    __syncthreads();

    const int ty = tid >> 4, tx = tid & 15;
    const int r = ty * 4, cc = tx * 4;

    float accA[4][4], accB[4][4];
    #pragma unroll
    for (int i = 0; i < 4; i++)
        #pragma unroll
        for (int j = 0; j < 4; j++) { accA[i][j] = sB1[cc + j]; accB[i][j] = 0.f; }

    #pragma unroll 2
    for (int k = 0; k < 64; k++) {
        const float4 xf = *(const float4*)&sXT[k * PADW + r];
        const float4 wd = *(const float4*)&sWdT[k * PADW + cc];
        const float4 wb = *(const float4*)&sWbT[k * PADW + cc];
        const float a0 = xf.x, a1 = xf.y, a2 = xf.z, a3 = xf.w;
        accA[0][0]+=a0*wd.x; accA[0][1]+=a0*wd.y; accA[0][2]+=a0*wd.z; accA[0][3]+=a0*wd.w;
        accA[1][0]+=a1*wd.x; accA[1][1]+=a1*wd.y; accA[1][2]+=a1*wd.z; accA[1][3]+=a1*wd.w;
        accA[2][0]+=a2*wd.x; accA[2][1]+=a2*wd.y; accA[2][2]+=a2*wd.z; accA[2][3]+=a2*wd.w;
        accA[3][0]+=a3*wd.x; accA[3][1]+=a3*wd.y; accA[3][2]+=a3*wd.z; accA[3][3]+=a3*wd.w;
        accB[0][0]+=a0*wb.x; accB[0][1]+=a0*wb.y; accB[0][2]+=a0*wb.z; accB[0][3]+=a0*wb.w;
        accB[1][0]+=a1*wb.x; accB[1][1]+=a1*wb.y; accB[1][2]+=a1*wb.z; accB[1][3]+=a1*wb.w;
        accB[2][0]+=a2*wb.x; accB[2][1]+=a2*wb.y; accB[2][2]+=a2*wb.z; accB[2][3]+=a2*wb.w;
        accB[3][0]+=a3*wb.x; accB[3][1]+=a3*wb.y; accB[3][2]+=a3*wb.z; accB[3][3]+=a3*wb.w;
    }

    #pragma unroll
    for (int i = 0; i < 4; i++) {
        const int node = n0 + r + i;
        if (node < n_nodes) {
            *(float4*)&A[(size_t)node * DIMV + cc] =
                make_float4(accA[i][0], accA[i][1], accA[i][2], accA[i][3]);
            *(float4*)&B[(size_t)node * DIMV + cc] =
                make_float4(accB[i][0], accB[i][1], accB[i][2], accB[i][3]);
        }
    }
}

// ---------------------------------------------------------------------------
// Edge kernel: h = ReLU(A[dst]+B[src]); msg = h @ W2^T + b2 ; atomicMax scatter
// 128-edge tiles, 8x4 register micro-tiles, persistent grid-stride.
// ---------------------------------------------------------------------------
__global__ __launch_bounds__(TPB, 4)
void edge_kernel(const float* __restrict__ A, const float* __restrict__ B,
                 const int* __restrict__ src, const int* __restrict__ dst,
                 const float* __restrict__ W2, const float* __restrict__ b2,
                 float* __restrict__ out, int n_edges)
{
    extern __shared__ float smem[];
    float* sW2T = smem;                 // [k][c] = W2[c][k]
    float* sB2  = sW2T + 64 * PADW;
    float* sHT  = sB2 + 64;             // [k][e]
    int*   sDst = (int*)(sHT + 64 * PADE);

    const int tid = threadIdx.x;

    for (int i = tid; i < 64 * 64; i += TPB) {
        int c = i >> 6, k = i & 63;
        sW2T[k * PADW + c] = W2[c * 64 + k];
    }
    if (tid < 64) sB2[tid] = b2[tid];
    __syncthreads();

    const int ty = tid >> 4, tx = tid & 15;
    const int r = ty * 8, cc = tx * 4;

    const int n_tiles = (n_edges + E_TILE - 1) / E_TILE;

    for (int tile = blockIdx.x; tile < n_tiles; tile += gridDim.x) {
        const int e0 = tile * E_TILE;

        // ---- gather + ReLU(A[dst]+B[src]) -> sHT[c][e], 2 threads/edge ----
        {
            const int e = tid >> 1;            // 0..127
            const int q = tid & 1;             // half of the 16 float4s
            const int eg = e0 + e;
            const bool valid = (eg < n_edges);
            int s = 0, d = 0;
            if (valid) { s = src[eg]; d = dst[eg]; }
            if (q == 0) sDst[e] = valid ? d : -1;
            const float4* a4 = (const float4*)(A + (size_t)d * DIMV);
            const float4* b4 = (const float4*)(B + (size_t)s * DIMV);
            #pragma unroll
            for (int v = 0; v < 8; v++) {
                const int c4 = q * 8 + v;
                float4 a = valid ? a4[c4] : make_float4(0.f,0.f,0.f,0.f);
                float4 b = valid ? b4[c4] : make_float4(0.f,0.f,0.f,0.f);
                const int c = c4 * 4;
                sHT[(c + 0) * PADE + e] = fmaxf(a.x + b.x, 0.f);
                sHT[(c + 1) * PADE + e] = fmaxf(a.y + b.y, 0.f);
                sHT[(c + 2) * PADE + e] = fmaxf(a.z + b.z, 0.f);
                sHT[(c + 3) * PADE + e] = fmaxf(a.w + b.w, 0.f);
            }
        }
        __syncthreads();

        // ---- GEMM2: msg[128e][64c] = h @ W2^T + b2 ----
        float acc[8][4];
        #pragma unroll
        for (int i = 0; i < 8; i++)
            #pragma unroll
            for (int j = 0; j < 4; j++) acc[i][j] = sB2[cc + j];

        #pragma unroll 2
        for (int k = 0; k < 64; k++) {
            const float4 af0 = *(const float4*)&sHT[k * PADE + r];
            const float4 af1 = *(const float4*)&sHT[k * PADE + r + 4];
            const float4 bf  = *(const float4*)&sW2T[k * PADW + cc];
            const float a0=af0.x, a1=af0.y, a2=af0.z, a3=af0.w;
            const float a4=af1.x, a5=af1.y, a6=af1.z, a7=af1.w;
            acc[0][0]+=a0*bf.x; acc[0][1]+=a0*bf.y; acc[0][2]+=a0*bf.z; acc[0][3]+=a0*bf.w;
            acc[1][0]+=a1*bf.x; acc[1][1]+=a1*bf.y; acc[1][2]+=a1*bf.z; acc[1][3]+=a1*bf.w;
            acc[2][0]+=a2*bf.x; acc[2][1]+=a2*bf.y; acc[2][2]+=a2*bf.z; acc[2][3]+=a2*bf.w;
            acc[3][0]+=a3*bf.x; acc[3][1]+=a3*bf.y; acc[3][2]+=a3*bf.z; acc[3][3]+=a3*bf.w;
            acc[4][0]+=a4*bf.x; acc[4][1]+=a4*bf.y; acc[4][2]+=a4*bf.z; acc[4][3]+=a4*bf.w;
            acc[5][0]+=a5*bf.x; acc[5][1]+=a5*bf.y; acc[5][2]+=a5*bf.z; acc[5][3]+=a5*bf.w;
            acc[6][0]+=a6*bf.x; acc[6][1]+=a6*bf.y; acc[6][2]+=a6*bf.z; acc[6][3]+=a6*bf.w;
            acc[7][0]+=a7*bf.x; acc[7][1]+=a7*bf.y; acc[7][2]+=a7*bf.z; acc[7][3]+=a7*bf.w;
        }

        // ---- scatter ----
        #pragma unroll
        for (int i = 0; i < 8; i++) {
            const int de = sDst[r + i];
            if (de >= 0) {
                float* op = out + (size_t)de * DIMV + cc;
                atomic_max_float(op + 0, acc[i][0]);
                atomic_max_float(op + 1, acc[i][1]);
                atomic_max_float(op + 2, acc[i][2]);
                atomic_max_float(op + 3, acc[i][3]);
            }
        }
        __syncthreads();   // sHT/sDst reuse next tile
    }
}

extern "C" void kernel_launch(void* const* d_in, const int* in_sizes, int n_in,
                              void* d_out, int out_size)
{
    const float* x   = (const float*)d_in[0];
    const int*   ei  = (const int*)d_in[1];
    const float* W1a = (const float*)d_in[2];
    const float* b1a = (const float*)d_in[3];
    const float* W2a = (const float*)d_in[4];
    const float* b2a = (const float*)d_in[5];
    const float* W1b = (const float*)d_in[6];
    const float* b1b = (const float*)d_in[7];
    const float* W2b = (const float*)d_in[8];
    const float* b2b = (const float*)d_in[9];

    const int n_nodes = in_sizes[0] / DIMV;
    const int n_edges = in_sizes[1] / 2;
    const int* src = ei;
    const int* dst = ei + n_edges;

    float* out = (float*)d_out;
    float *h1, *Abuf, *Bbuf;
    cudaGetSymbolAddress((void**)&h1,   g_h1);
    cudaGetSymbolAddress((void**)&Abuf, g_A);
    cudaGetSymbolAddress((void**)&Bbuf, g_B);

    cudaFuncSetAttribute(pre_kernel,
                         cudaFuncAttributeMaxDynamicSharedMemorySize, PRE_SMEM_BYTES);
    cudaFuncSetAttribute(edge_kernel,
                         cudaFuncAttributeMaxDynamicSharedMemorySize, EDGE_SMEM_BYTES);

    const int n_feat = n_nodes * DIMV;
    const int init_blocks = (n_feat + TPB - 1) / TPB;
    const int pre_blocks  = (n_nodes + 63) / 64;
    const int edge_blocks = 148 * 4;

    // ---- layer 1 ----
    pre_kernel<<<pre_blocks, TPB, PRE_SMEM_BYTES>>>(x, W1a, b1a, Abuf, Bbuf, n_nodes, 0);
    init_neg_inf_kernel<<<init_blocks, TPB>>>(h1, n_feat);
    edge_kernel<<<edge_blocks, TPB, EDGE_SMEM_BYTES>>>(Abuf, Bbuf, src, dst,
                                                       W2a, b2a, h1, n_edges);
    // (h1 finalize fused into layer-2 pre_kernel via finite_fix)

    // ---- layer 2 ----
    pre_kernel<<<pre_blocks, TPB, PRE_SMEM_BYTES>>>(h1, W1b, b1b, Abuf, Bbuf, n_nodes, 1);
    init_neg_inf_kernel<<<init_blocks, TPB>>>(out, n_feat);
    edge_kernel<<<edge_blocks, TPB, EDGE_SMEM_BYTES>>>(Abuf, Bbuf, src, dst,
                                                       W2b, b2b, out, n_edges);
    finalize_kernel<<<init_blocks, TPB>>>(out, n_feat);
}

// round 4
// speedup vs baseline: 2.2280x; 1.3924x over previous
#include <cuda_runtime.h>
#include <cstdint>
#include <math.h>

// ----------------------------------------------------------------------------
// StackDevConv, factorized + dst-sorted edges:
//   W1 = [Wa | Wb];  A[n] = x[n]@(Wa-Wb)^T + b1 ;  B[n] = x[n]@Wb^T
//   per edge: h = ReLU(A[dst]+B[src]);  msg = h @ W2^T + b2
//   out[n] = segment_max(msg, dst) ; empty -> 0
// Edges counting-sorted by dst once per launch (order-invariant exact max),
// reused by both layers: slashes atomics ~5x and makes A[dst] L1-local.
// edge_index is int32.
// ----------------------------------------------------------------------------

#define DIMV    64
#define TPB     256
#define PADW    68
#define E_TILE  128
#define PADE    132
#define MAX_NODES 50000
#define MAX_EDGES 800000

__device__ float g_h1[MAX_NODES * DIMV];
__device__ float g_A [MAX_NODES * DIMV];
__device__ float g_B [MAX_NODES * DIMV];
__device__ int   g_count [MAX_NODES];
__device__ int   g_offset[MAX_NODES];
__device__ int   g_src_s[MAX_EDGES];
__device__ int   g_dst_s[MAX_EDGES];

#define PRE_SMEM_FLOATS (64*PADW*3 + 64)
#define PRE_SMEM_BYTES  (PRE_SMEM_FLOATS*4)
#define EDGE_SMEM_FLOATS (64*PADW + 64 + 64*PADE + 128)
#define EDGE_SMEM_BYTES  (EDGE_SMEM_FLOATS*4)

__device__ __forceinline__ void atomic_max_float(float* addr, float value) {
    unsigned int ui = __float_as_uint(value);
    if ((int)ui >= 0) atomicMax((int*)addr, (int)ui);
    else              atomicMin((unsigned int*)addr, ui);
}

__global__ void init_neg_inf_kernel(float* p, int n) {
    int i = blockIdx.x * blockDim.x + threadIdx.x;
    if (i < n) ((unsigned int*)p)[i] = 0xFF800000u;
}

__global__ void finalize_kernel(float* p, int n) {
    int i = blockIdx.x * blockDim.x + threadIdx.x;
    if (i < n) { float v = p[i]; if (!isfinite(v)) p[i] = 0.0f; }
}

// ---------------- counting sort by dst ----------------
__global__ void zero_count_kernel(int n_nodes) {
    int i = blockIdx.x * blockDim.x + threadIdx.x;
    if (i < n_nodes) g_count[i] = 0;
}

__global__ void hist_kernel(const int* __restrict__ dst, int n_edges) {
    int i = blockIdx.x * blockDim.x + threadIdx.x;
    if (i < n_edges) atomicAdd(&g_count[dst[i]], 1);
}

__global__ void scan_kernel(int n_nodes) {
    __shared__ int partial[1024];
    const int tid = threadIdx.x;
    const int chunk = (n_nodes + 1023) / 1024;
    const int begin = tid * chunk;
    const int end   = min(begin + chunk, n_nodes);
    int s = 0;
    for (int i = begin; i < end; i++) s += g_count[i];
    partial[tid] = s;
    __syncthreads();
    for (int off = 1; off < 1024; off <<= 1) {
        int v = partial[tid];
        int add = (tid >= off) ? partial[tid - off] : 0;
        __syncthreads();
        partial[tid] = v + add;
        __syncthreads();
    }
    int base = (tid > 0) ? partial[tid - 1] : 0;
    for (int i = begin; i < end; i++) { g_offset[i] = base; base += g_count[i]; }
}

__global__ void scatter_kernel(const int* __restrict__ src,
                               const int* __restrict__ dst, int n_edges) {
    int i = blockIdx.x * blockDim.x + threadIdx.x;
    if (i < n_edges) {
        int d = dst[i];
        int pos = atomicAdd(&g_offset[d], 1);
        g_src_s[pos] = src[i];
        g_dst_s[pos] = d;
    }
}

// ---------------- per-node precompute ----------------
__global__ __launch_bounds__(TPB, 3)
void pre_kernel(const float* __restrict__ x,
                const float* __restrict__ W1, const float* __restrict__ b1,
                float* __restrict__ A, float* __restrict__ B,
                int n_nodes, int finite_fix)
{
    extern __shared__ float smem[];
    float* sWdT = smem;
    float* sWbT = sWdT + 64 * PADW;
    float* sB1  = sWbT + 64 * PADW;
    float* sXT  = sB1 + 64;

    const int tid = threadIdx.x;

    for (int i = tid; i < 64 * 64; i += TPB) {
        int c = i >> 6, k = i & 63;
        float wa = W1[c * 128 + k];
        float wb = W1[c * 128 + 64 + k];
        sWdT[k * PADW + c] = wa - wb;
        sWbT[k * PADW + c] = wb;
    }
    if (tid < 64) sB1[tid] = b1[tid];

    const int n0 = blockIdx.x * 64;
    {
        const int e = tid >> 2;
        const int q = tid & 3;
        const int node = n0 + e;
        const float4* xr = (const float4*)(x + (size_t)(node < n_nodes ? node : 0) * DIMV);
        #pragma unroll
        for (int v = 0; v < 4; v++) {
            const int c4 = q * 4 + v;
            float4 a = (node < n_nodes) ? xr[c4] : make_float4(0.f,0.f,0.f,0.f);
            if (finite_fix) {
                if (!isfinite(a.x)) a.x = 0.f;
                if (!isfinite(a.y)) a.y = 0.f;
                if (!isfinite(a.z)) a.z = 0.f;
                if (!isfinite(a.w)) a.w = 0.f;
            }
            const int c = c4 * 4;
            sXT[(c + 0) * PADW + e] = a.x;
            sXT[(c + 1) * PADW + e] = a.y;
            sXT[(c + 2) * PADW + e] = a.z;
            sXT[(c + 3) * PADW + e] = a.w;
        }
    }
    __syncthreads();

    const int ty = tid >> 4, tx = tid & 15;
    const int r = ty * 4, cc = tx * 4;

    float accA[4][4], accB[4][4];
    #pragma unroll
    for (int i = 0; i < 4; i++)
        #pragma unroll
        for (int j = 0; j < 4; j++) { accA[i][j] = sB1[cc + j]; accB[i][j] = 0.f; }

    #pragma unroll 2
    for (int k = 0; k < 64; k++) {
        const float4 xf = *(const float4*)&sXT[k * PADW + r];
        const float4 wd = *(const float4*)&sWdT[k * PADW + cc];
        const float4 wb = *(const float4*)&sWbT[k * PADW + cc];
        const float a0 = xf.x, a1 = xf.y, a2 = xf.z, a3 = xf.w;
        accA[0][0]+=a0*wd.x; accA[0][1]+=a0*wd.y; accA[0][2]+=a0*wd.z; accA[0][3]+=a0*wd.w;
        accA[1][0]+=a1*wd.x; accA[1][1]+=a1*wd.y; accA[1][2]+=a1*wd.z; accA[1][3]+=a1*wd.w;
        accA[2][0]+=a2*wd.x; accA[2][1]+=a2*wd.y; accA[2][2]+=a2*wd.z; accA[2][3]+=a2*wd.w;
        accA[3][0]+=a3*wd.x; accA[3][1]+=a3*wd.y; accA[3][2]+=a3*wd.z; accA[3][3]+=a3*wd.w;
        accB[0][0]+=a0*wb.x; accB[0][1]+=a0*wb.y; accB[0][2]+=a0*wb.z; accB[0][3]+=a0*wb.w;
        accB[1][0]+=a1*wb.x; accB[1][1]+=a1*wb.y; accB[1][2]+=a1*wb.z; accB[1][3]+=a1*wb.w;
        accB[2][0]+=a2*wb.x; accB[2][1]+=a2*wb.y; accB[2][2]+=a2*wb.z; accB[2][3]+=a2*wb.w;
        accB[3][0]+=a3*wb.x; accB[3][1]+=a3*wb.y; accB[3][2]+=a3*wb.z; accB[3][3]+=a3*wb.w;
    }

    #pragma unroll
    for (int i = 0; i < 4; i++) {
        const int node = n0 + r + i;
        if (node < n_nodes) {
            *(float4*)&A[(size_t)node * DIMV + cc] =
                make_float4(accA[i][0], accA[i][1], accA[i][2], accA[i][3]);
            *(float4*)&B[(size_t)node * DIMV + cc] =
                make_float4(accB[i][0], accB[i][1], accB[i][2], accB[i][3]);
        }
    }
}

// ---------------- edge kernel on sorted edges ----------------
__global__ __launch_bounds__(TPB, 4)
void edge_kernel(const float* __restrict__ A, const float* __restrict__ B,
                 const float* __restrict__ W2, const float* __restrict__ b2,
                 float* __restrict__ out, int n_edges)
{
    extern __shared__ float smem[];
    float* sW2T = smem;
    float* sB2  = sW2T + 64 * PADW;
    float* sHT  = sB2 + 64;
    int*   sDst = (int*)(sHT + 64 * PADE);

    const int tid = threadIdx.x;

    for (int i = tid; i < 64 * 64; i += TPB) {
        int c = i >> 6, k = i & 63;
        sW2T[k * PADW + c] = W2[c * 64 + k];
    }
    if (tid < 64) sB2[tid] = b2[tid];
    __syncthreads();

    const int ty = tid >> 4, tx = tid & 15;
    const int r = ty * 8, cc = tx * 4;

    const int n_tiles = (n_edges + E_TILE - 1) / E_TILE;

    for (int tile = blockIdx.x; tile < n_tiles; tile += gridDim.x) {
        const int e0 = tile * E_TILE;

        // gather + ReLU(A[dst]+B[src]) -> sHT[c][e], 2 threads/edge
        {
            const int e = tid >> 1;
            const int q = tid & 1;
            const int eg = e0 + e;
            const bool valid = (eg < n_edges);
            int s = 0, d = 0;
            if (valid) { s = g_src_s[eg]; d = g_dst_s[eg]; }
            if (q == 0) sDst[e] = valid ? d : -1;
            const float4* a4 = (const float4*)(A + (size_t)d * DIMV);
            const float4* b4 = (const float4*)(B + (size_t)s * DIMV);
            #pragma unroll
            for (int v = 0; v < 8; v++) {
                const int c4 = q * 8 + v;
                float4 a = valid ? a4[c4] : make_float4(0.f,0.f,0.f,0.f);
                float4 b = valid ? b4[c4] : make_float4(0.f,0.f,0.f,0.f);
                const int c = c4 * 4;
                sHT[(c + 0) * PADE + e] = fmaxf(a.x + b.x, 0.f);
                sHT[(c + 1) * PADE + e] = fmaxf(a.y + b.y, 0.f);
                sHT[(c + 2) * PADE + e] = fmaxf(a.z + b.z, 0.f);
                sHT[(c + 3) * PADE + e] = fmaxf(a.w + b.w, 0.f);
            }
        }
        __syncthreads();

        // GEMM2: msg[128e][64c] = h @ W2^T + b2
        float acc[8][4];
        #pragma unroll
        for (int i = 0; i < 8; i++)
            #pragma unroll
            for (int j = 0; j < 4; j++) acc[i][j] = sB2[cc + j];

        #pragma unroll 2
        for (int k = 0; k < 64; k++) {
            const float4 af0 = *(const float4*)&sHT[k * PADE + r];
            const float4 af1 = *(const float4*)&sHT[k * PADE + r + 4];
            const float4 bf  = *(const float4*)&sW2T[k * PADW + cc];
            const float a0=af0.x, a1=af0.y, a2=af0.z, a3=af0.w;
            const float a4=af1.x, a5=af1.y, a6=af1.z, a7=af1.w;
            acc[0][0]+=a0*bf.x; acc[0][1]+=a0*bf.y; acc[0][2]+=a0*bf.z; acc[0][3]+=a0*bf.w;
            acc[1][0]+=a1*bf.x; acc[1][1]+=a1*bf.y; acc[1][2]+=a1*bf.z; acc[1][3]+=a1*bf.w;
            acc[2][0]+=a2*bf.x; acc[2][1]+=a2*bf.y; acc[2][2]+=a2*bf.z; acc[2][3]+=a2*bf.w;
            acc[3][0]+=a3*bf.x; acc[3][1]+=a3*bf.y; acc[3][2]+=a3*bf.z; acc[3][3]+=a3*bf.w;
            acc[4][0]+=a4*bf.x; acc[4][1]+=a4*bf.y; acc[4][2]+=a4*bf.z; acc[4][3]+=a4*bf.w;
            acc[5][0]+=a5*bf.x; acc[5][1]+=a5*bf.y; acc[5][2]+=a5*bf.z; acc[5][3]+=a5*bf.w;
            acc[6][0]+=a6*bf.x; acc[6][1]+=a6*bf.y; acc[6][2]+=a6*bf.z; acc[6][3]+=a6*bf.w;
            acc[7][0]+=a7*bf.x; acc[7][1]+=a7*bf.y; acc[7][2]+=a7*bf.z; acc[7][3]+=a7*bf.w;
        }

        // segmented emit: carry max through equal-dst runs, atomic at run end
        #pragma unroll
        for (int i = 0; i < 8; i++) {
            const int de = sDst[r + i];
            const bool last = (i == 7) || (sDst[r + i + 1] != de);
            if (!last) {
                acc[i+1][0] = fmaxf(acc[i+1][0], acc[i][0]);
                acc[i+1][1] = fmaxf(acc[i+1][1], acc[i][1]);
                acc[i+1][2] = fmaxf(acc[i+1][2], acc[i][2]);
                acc[i+1][3] = fmaxf(acc[i+1][3], acc[i][3]);
            } else if (de >= 0) {
                float* op = out + (size_t)de * DIMV + cc;
                atomic_max_float(op + 0, acc[i][0]);
                atomic_max_float(op + 1, acc[i][1]);
                atomic_max_float(op + 2, acc[i][2]);
                atomic_max_float(op + 3, acc[i][3]);
            }
        }
        __syncthreads();
    }
}

extern "C" void kernel_launch(void* const* d_in, const int* in_sizes, int n_in,
                              void* d_out, int out_size)
{
    const float* x   = (const float*)d_in[0];
    const int*   ei  = (const int*)d_in[1];
    const float* W1a = (const float*)d_in[2];
    const float* b1a = (const float*)d_in[3];
    const float* W2a = (const float*)d_in[4];
    const float* b2a = (const float*)d_in[5];
    const float* W1b = (const float*)d_in[6];
    const float* b1b = (const float*)d_in[7];
    const float* W2b = (const float*)d_in[8];
    const float* b2b = (const float*)d_in[9];

    const int n_nodes = in_sizes[0] / DIMV;
    const int n_edges = in_sizes[1] / 2;
    const int* src = ei;
    const int* dst = ei + n_edges;

    float* out = (float*)d_out;
    float *h1, *Abuf, *Bbuf;
    cudaGetSymbolAddress((void**)&h1,   g_h1);
    cudaGetSymbolAddress((void**)&Abuf, g_A);
    cudaGetSymbolAddress((void**)&Bbuf, g_B);

    cudaFuncSetAttribute(pre_kernel,
                         cudaFuncAttributeMaxDynamicSharedMemorySize, PRE_SMEM_BYTES);
    cudaFuncSetAttribute(edge_kernel,
                         cudaFuncAttributeMaxDynamicSharedMemorySize, EDGE_SMEM_BYTES);

    const int n_feat = n_nodes * DIMV;
    const int init_blocks = (n_feat + TPB - 1) / TPB;
    const int pre_blocks  = (n_nodes + 63) / 64;
    const int edge_blocks = 148 * 4;
    const int eb = (n_edges + TPB - 1) / TPB;
    const int nb = (n_nodes + TPB - 1) / TPB;

    // ---- counting sort by dst (once; reused by both layers) ----
    zero_count_kernel<<<nb, TPB>>>(n_nodes);
    hist_kernel<<<eb, TPB>>>(dst, n_edges);
    scan_kernel<<<1, 1024>>>(n_nodes);
    scatter_kernel<<<eb, TPB>>>(src, dst, n_edges);

    // ---- layer 1 ----
    pre_kernel<<<pre_blocks, TPB, PRE_SMEM_BYTES>>>(x, W1a, b1a, Abuf, Bbuf, n_nodes, 0);
    init_neg_inf_kernel<<<init_blocks, TPB>>>(h1, n_feat);
    edge_kernel<<<edge_blocks, TPB, EDGE_SMEM_BYTES>>>(Abuf, Bbuf, W2a, b2a, h1, n_edges);

    // ---- layer 2 (h1 finalize fused via finite_fix) ----
    pre_kernel<<<pre_blocks, TPB, PRE_SMEM_BYTES>>>(h1, W1b, b1b, Abuf, Bbuf, n_nodes, 1);
    init_neg_inf_kernel<<<init_blocks, TPB>>>(out, n_feat);
    edge_kernel<<<edge_blocks, TPB, EDGE_SMEM_BYTES>>>(Abuf, Bbuf, W2b, b2b, out, n_edges);
    finalize_kernel<<<init_blocks, TPB>>>(out, n_feat);
}

// round 5
// speedup vs baseline: 2.8814x; 1.2933x over previous
#include <cuda_runtime.h>
#include <cstdint>
#include <math.h>

// ----------------------------------------------------------------------------
// StackDevConv, factorized + dst-sorted edges + tf32 tensor-core edge GEMM.
//   W1 = [Wa | Wb];  A[n] = x[n]@(Wa-Wb)^T + b1 ;  B[n] = x[n]@Wb^T   (fp32)
//   per edge: h = ReLU(A[dst]+B[src]);  msg = h @ W2^T + b2           (tf32 mma)
//   out[n] = segment_max(msg, dst) ; empty -> 0
// ----------------------------------------------------------------------------

#define DIMV    64
#define TPB     256
#define PADW    68
#define E_TILE  128
#define MAX_NODES 50000
#define MAX_EDGES 800000

#define SH 68    // sH  stride (uint32 tf32)  -> A-frag LDS conflict-free
#define SW 72    // sW2 stride (uint32 tf32)  -> B-frag LDS conflict-free
#define SMS 68   // sMsg stride (float)

__device__ float g_h1[MAX_NODES * DIMV];
__device__ float g_A [MAX_NODES * DIMV];
__device__ float g_B [MAX_NODES * DIMV];
__device__ int   g_count [MAX_NODES];
__device__ int   g_offset[MAX_NODES];
__device__ int   g_src_s[MAX_EDGES];
__device__ int   g_dst_s[MAX_EDGES];

#define PRE_SMEM_FLOATS (64*PADW*3 + 64)
#define PRE_SMEM_BYTES  (PRE_SMEM_FLOATS*4)

// edge smem (4B words): sW2tf[64*SW] + sB2[64] + sH[128*SH] + sMsg[128*SMS] + sDst[128]
#define EDGE_SMEM_WORDS (64*SW + 64 + 128*SH + 128*SMS + 128)
#define EDGE_SMEM_BYTES (EDGE_SMEM_WORDS*4)

__device__ __forceinline__ void atomic_max_float(float* addr, float value) {
    unsigned int ui = __float_as_uint(value);
    if ((int)ui >= 0) atomicMax((int*)addr, (int)ui);
    else              atomicMin((unsigned int*)addr, ui);
}

__device__ __forceinline__ unsigned int f2tf(float x) {
    unsigned int r;
    asm("cvt.rna.tf32.f32 %0, %1;" : "=r"(r) : "f"(x));
    return r;
}

__global__ void init_neg_inf_kernel(float* p, int n) {
    int i = blockIdx.x * blockDim.x + threadIdx.x;
    if (i < n) ((unsigned int*)p)[i] = 0xFF800000u;
}

__global__ void finalize_kernel(float* p, int n) {
    int i = blockIdx.x * blockDim.x + threadIdx.x;
    if (i < n) { float v = p[i]; if (!isfinite(v)) p[i] = 0.0f; }
}

// ---------------- counting sort by dst ----------------
__global__ void zero_count_kernel(int n_nodes) {
    int i = blockIdx.x * blockDim.x + threadIdx.x;
    if (i < n_nodes) g_count[i] = 0;
}

__global__ void hist_kernel(const int* __restrict__ dst, int n_edges) {
    int i = blockIdx.x * blockDim.x + threadIdx.x;
    if (i < n_edges) atomicAdd(&g_count[dst[i]], 1);
}

__global__ void scan_kernel(int n_nodes) {
    __shared__ int partial[1024];
    const int tid = threadIdx.x;
    const int chunk = (n_nodes + 1023) / 1024;
    const int begin = tid * chunk;
    const int end   = min(begin + chunk, n_nodes);
    int s = 0;
    for (int i = begin; i < end; i++) s += g_count[i];
    partial[tid] = s;
    __syncthreads();
    for (int off = 1; off < 1024; off <<= 1) {
        int v = partial[tid];
        int add = (tid >= off) ? partial[tid - off] : 0;
        __syncthreads();
        partial[tid] = v + add;
        __syncthreads();
    }
    int base = (tid > 0) ? partial[tid - 1] : 0;
    for (int i = begin; i < end; i++) { g_offset[i] = base; base += g_count[i]; }
}

__global__ void scatter_kernel(const int* __restrict__ src,
                               const int* __restrict__ dst, int n_edges) {
    int i = blockIdx.x * blockDim.x + threadIdx.x;
    if (i < n_edges) {
        int d = dst[i];
        int pos = atomicAdd(&g_offset[d], 1);
        g_src_s[pos] = src[i];
        g_dst_s[pos] = d;
    }
}

// ---------------- per-node precompute (fp32, exact) ----------------
__global__ __launch_bounds__(TPB, 3)
void pre_kernel(const float* __restrict__ x,
                const float* __restrict__ W1, const float* __restrict__ b1,
                float* __restrict__ A, float* __restrict__ B,
                int n_nodes, int finite_fix)
{
    extern __shared__ float smem[];
    float* sWdT = smem;
    float* sWbT = sWdT + 64 * PADW;
    float* sB1  = sWbT + 64 * PADW;
    float* sXT  = sB1 + 64;

    const int tid = threadIdx.x;

    for (int i = tid; i < 64 * 64; i += TPB) {
        int c = i >> 6, k = i & 63;
        float wa = W1[c * 128 + k];
        float wb = W1[c * 128 + 64 + k];
        sWdT[k * PADW + c] = wa - wb;
        sWbT[k * PADW + c] = wb;
    }
    if (tid < 64) sB1[tid] = b1[tid];

    const int n0 = blockIdx.x * 64;
    {
        const int e = tid >> 2;
        const int q = tid & 3;
        const int node = n0 + e;
        const float4* xr = (const float4*)(x + (size_t)(node < n_nodes ? node : 0) * DIMV);
        #pragma unroll
        for (int v = 0; v < 4; v++) {
            const int c4 = q * 4 + v;
            float4 a = (node < n_nodes) ? xr[c4] : make_float4(0.f,0.f,0.f,0.f);
            if (finite_fix) {
                if (!isfinite(a.x)) a.x = 0.f;
                if (!isfinite(a.y)) a.y = 0.f;
                if (!isfinite(a.z)) a.z = 0.f;
                if (!isfinite(a.w)) a.w = 0.f;
            }
            const int c = c4 * 4;
            sXT[(c + 0) * PADW + e] = a.x;
            sXT[(c + 1) * PADW + e] = a.y;
            sXT[(c + 2) * PADW + e] = a.z;
            sXT[(c + 3) * PADW + e] = a.w;
        }
    }
    __syncthreads();

    const int ty = tid >> 4, tx = tid & 15;
    const int r = ty * 4, cc = tx * 4;

    float accA[4][4], accB[4][4];
    #pragma unroll
    for (int i = 0; i < 4; i++)
        #pragma unroll
        for (int j = 0; j < 4; j++) { accA[i][j] = sB1[cc + j]; accB[i][j] = 0.f; }

    #pragma unroll 2
    for (int k = 0; k < 64; k++) {
        const float4 xf = *(const float4*)&sXT[k * PADW + r];
        const float4 wd = *(const float4*)&sWdT[k * PADW + cc];
        const float4 wb = *(const float4*)&sWbT[k * PADW + cc];
        const float a0 = xf.x, a1 = xf.y, a2 = xf.z, a3 = xf.w;
        accA[0][0]+=a0*wd.x; accA[0][1]+=a0*wd.y; accA[0][2]+=a0*wd.z; accA[0][3]+=a0*wd.w;
        accA[1][0]+=a1*wd.x; accA[1][1]+=a1*wd.y; accA[1][2]+=a1*wd.z; accA[1][3]+=a1*wd.w;
        accA[2][0]+=a2*wd.x; accA[2][1]+=a2*wd.y; accA[2][2]+=a2*wd.z; accA[2][3]+=a2*wd.w;
        accA[3][0]+=a3*wd.x; accA[3][1]+=a3*wd.y; accA[3][2]+=a3*wd.z; accA[3][3]+=a3*wd.w;
        accB[0][0]+=a0*wb.x; accB[0][1]+=a0*wb.y; accB[0][2]+=a0*wb.z; accB[0][3]+=a0*wb.w;
        accB[1][0]+=a1*wb.x; accB[1][1]+=a1*wb.y; accB[1][2]+=a1*wb.z; accB[1][3]+=a1*wb.w;
        accB[2][0]+=a2*wb.x; accB[2][1]+=a2*wb.y; accB[2][2]+=a2*wb.z; accB[2][3]+=a2*wb.w;
        accB[3][0]+=a3*wb.x; accB[3][1]+=a3*wb.y; accB[3][2]+=a3*wb.z; accB[3][3]+=a3*wb.w;
    }

    #pragma unroll
    for (int i = 0; i < 4; i++) {
        const int node = n0 + r + i;
        if (node < n_nodes) {
            *(float4*)&A[(size_t)node * DIMV + cc] =
                make_float4(accA[i][0], accA[i][1], accA[i][2], accA[i][3]);
            *(float4*)&B[(size_t)node * DIMV + cc] =
                make_float4(accB[i][0], accB[i][1], accB[i][2], accB[i][3]);
        }
    }
}

// ---------------- edge kernel: tf32 mma GEMM2 + run-merged atomic scatter ----
__global__ __launch_bounds__(TPB, 2)
void edge_kernel(const float* __restrict__ A, const float* __restrict__ B,
                 const float* __restrict__ W2, const float* __restrict__ b2,
                 float* __restrict__ out, int n_edges)
{
    extern __shared__ unsigned int usmem[];
    unsigned int* sW2tf = usmem;                       // [k][n] tf32, stride SW
    float*        sB2   = (float*)(sW2tf + 64 * SW);
    unsigned int* sH    = (unsigned int*)(sB2 + 64);   // [e][k] tf32, stride SH
    float*        sMsg  = (float*)(sH + 128 * SH);     // [e][n], stride SMS
    int*          sDst  = (int*)(sMsg + 128 * SMS);

    const int tid  = threadIdx.x;
    const int wid  = tid >> 5;
    const int lane = tid & 31;
    const int grp  = lane >> 2;      // 0..7
    const int qd   = lane & 3;       // 0..3

    // stage W2^T as tf32: sW2tf[k*SW + n] = tf32(W2[n][k])
    for (int i = tid; i < 64 * 64; i += TPB) {
        int n = i >> 6, k = i & 63;
        sW2tf[k * SW + n] = f2tf(W2[n * 64 + k]);
    }
    if (tid < 64) sB2[tid] = b2[tid];
    __syncthreads();

    const int ty = tid >> 4, tx = tid & 15;
    const int r = ty * 8, cc = tx * 4;

    const int n_tiles = (n_edges + E_TILE - 1) / E_TILE;

    for (int tile = blockIdx.x; tile < n_tiles; tile += gridDim.x) {
        const int e0 = tile * E_TILE;

        // ---- gather + ReLU -> sH[e][k] (tf32), 2 threads/edge ----
        {
            const int e = tid >> 1;
            const int q = tid & 1;
            const int eg = e0 + e;
            const bool valid = (eg < n_edges);
            int s = 0, d = 0;
            if (valid) { s = g_src_s[eg]; d = g_dst_s[eg]; }
            if (q == 0) sDst[e] = valid ? d : -1;
            const float4* a4 = (const float4*)(A + (size_t)d * DIMV);
            const float4* b4 = (const float4*)(B + (size_t)s * DIMV);
            #pragma unroll
            for (int v = 0; v < 8; v++) {
                const int c4 = q * 8 + v;
                float4 a = valid ? a4[c4] : make_float4(0.f,0.f,0.f,0.f);
                float4 b = valid ? b4[c4] : make_float4(0.f,0.f,0.f,0.f);
                const int c = c4 * 4;
                sH[e * SH + c + 0] = f2tf(fmaxf(a.x + b.x, 0.f));
                sH[e * SH + c + 1] = f2tf(fmaxf(a.y + b.y, 0.f));
                sH[e * SH + c + 2] = f2tf(fmaxf(a.z + b.z, 0.f));
                sH[e * SH + c + 3] = f2tf(fmaxf(a.w + b.w, 0.f));
            }
        }
        __syncthreads();

        // ---- tf32 mma: warp wid handles edges [wid*16, wid*16+16) ----
        {
            const int m0 = wid * 16;
            unsigned int af[8][4];
            #pragma unroll
            for (int ks = 0; ks < 8; ks++) {
                const int k0 = ks * 8;
                af[ks][0] = sH[(m0 + grp    ) * SH + k0 + qd    ];
                af[ks][1] = sH[(m0 + grp + 8) * SH + k0 + qd    ];
                af[ks][2] = sH[(m0 + grp    ) * SH + k0 + qd + 4];
                af[ks][3] = sH[(m0 + grp + 8) * SH + k0 + qd + 4];
            }
            #pragma unroll
            for (int nt = 0; nt < 8; nt++) {
                const int n0 = nt * 8;
                float c0 = 0.f, c1 = 0.f, c2 = 0.f, c3 = 0.f;
                #pragma unroll
                for (int ks = 0; ks < 8; ks++) {
                    const int k0 = ks * 8;
                    unsigned int b0 = sW2tf[(k0 + qd    ) * SW + n0 + grp];
                    unsigned int b1 = sW2tf[(k0 + qd + 4) * SW + n0 + grp];
                    asm volatile(
                        "mma.sync.aligned.m16n8k8.row.col.f32.tf32.tf32.f32 "
                        "{%0,%1,%2,%3}, {%4,%5,%6,%7}, {%8,%9}, {%0,%1,%2,%3};"
                        : "+f"(c0), "+f"(c1), "+f"(c2), "+f"(c3)
                        : "r"(af[ks][0]), "r"(af[ks][1]), "r"(af[ks][2]), "r"(af[ks][3]),
                          "r"(b0), "r"(b1));
                }
                const int col = n0 + 2 * qd;
                const float bb0 = sB2[col], bb1 = sB2[col + 1];
                sMsg[(m0 + grp    ) * SMS + col    ] = c0 + bb0;
                sMsg[(m0 + grp    ) * SMS + col + 1] = c1 + bb1;
                sMsg[(m0 + grp + 8) * SMS + col    ] = c2 + bb0;
                sMsg[(m0 + grp + 8) * SMS + col + 1] = c3 + bb1;
            }
        }
        __syncthreads();

        // ---- scatter: run-merge within 8-edge chains, atomics at run ends ----
        {
            float4 cur = *(const float4*)&sMsg[r * SMS + cc];
            #pragma unroll
            for (int i = 0; i < 8; i++) {
                const int de = sDst[r + i];
                const bool last = (i == 7) || (sDst[r + i + 1] != de);
                if (!last) {
                    const float4 nx = *(const float4*)&sMsg[(r + i + 1) * SMS + cc];
                    cur.x = fmaxf(cur.x, nx.x);
                    cur.y = fmaxf(cur.y, nx.y);
                    cur.z = fmaxf(cur.z, nx.z);
                    cur.w = fmaxf(cur.w, nx.w);
                } else {
                    if (de >= 0) {
                        float* op = out + (size_t)de * DIMV + cc;
                        atomic_max_float(op + 0, cur.x);
                        atomic_max_float(op + 1, cur.y);
                        atomic_max_float(op + 2, cur.z);
                        atomic_max_float(op + 3, cur.w);
                    }
                    if (i < 7)
                        cur = *(const float4*)&sMsg[(r + i + 1) * SMS + cc];
                }
            }
        }
        __syncthreads();
    }
}

extern "C" void kernel_launch(void* const* d_in, const int* in_sizes, int n_in,
                              void* d_out, int out_size)
{
    const float* x   = (const float*)d_in[0];
    const int*   ei  = (const int*)d_in[1];
    const float* W1a = (const float*)d_in[2];
    const float* b1a = (const float*)d_in[3];
    const float* W2a = (const float*)d_in[4];
    const float* b2a = (const float*)d_in[5];
    const float* W1b = (const float*)d_in[6];
    const float* b1b = (const float*)d_in[7];
    const float* W2b = (const float*)d_in[8];
    const float* b2b = (const float*)d_in[9];

    const int n_nodes = in_sizes[0] / DIMV;
    const int n_edges = in_sizes[1] / 2;
    const int* src = ei;
    const int* dst = ei + n_edges;

    float* out = (float*)d_out;
    float *h1, *Abuf, *Bbuf;
    cudaGetSymbolAddress((void**)&h1,   g_h1);
    cudaGetSymbolAddress((void**)&Abuf, g_A);
    cudaGetSymbolAddress((void**)&Bbuf, g_B);

    cudaFuncSetAttribute(pre_kernel,
                         cudaFuncAttributeMaxDynamicSharedMemorySize, PRE_SMEM_BYTES);
    cudaFuncSetAttribute(edge_kernel,
                         cudaFuncAttributeMaxDynamicSharedMemorySize, EDGE_SMEM_BYTES);

    const int n_feat = n_nodes * DIMV;
    const int init_blocks = (n_feat + TPB - 1) / TPB;
    const int pre_blocks  = (n_nodes + 63) / 64;
    const int edge_blocks = 148 * 2;
    const int eb = (n_edges + TPB - 1) / TPB;
    const int nb = (n_nodes + TPB - 1) / TPB;

    // ---- counting sort by dst (once; reused by both layers) ----
    zero_count_kernel<<<nb, TPB>>>(n_nodes);
    hist_kernel<<<eb, TPB>>>(dst, n_edges);
    scan_kernel<<<1, 1024>>>(n_nodes);
    scatter_kernel<<<eb, TPB>>>(src, dst, n_edges);

    // ---- layer 1 ----
    pre_kernel<<<pre_blocks, TPB, PRE_SMEM_BYTES>>>(x, W1a, b1a, Abuf, Bbuf, n_nodes, 0);
    init_neg_inf_kernel<<<init_blocks, TPB>>>(h1, n_feat);
    edge_kernel<<<edge_blocks, TPB, EDGE_SMEM_BYTES>>>(Abuf, Bbuf, W2a, b2a, h1, n_edges);

    // ---- layer 2 (h1 finalize fused via finite_fix) ----
    pre_kernel<<<pre_blocks, TPB, PRE_SMEM_BYTES>>>(h1, W1b, b1b, Abuf, Bbuf, n_nodes, 1);
    init_neg_inf_kernel<<<init_blocks, TPB>>>(out, n_feat);
    edge_kernel<<<edge_blocks, TPB, EDGE_SMEM_BYTES>>>(Abuf, Bbuf, W2b, b2b, out, n_edges);
    finalize_kernel<<<init_blocks, TPB>>>(out, n_feat);
}

// round 6
// speedup vs baseline: 3.0219x; 1.0487x over previous
#include <cuda_runtime.h>
#include <cstdint>
#include <math.h>

// ----------------------------------------------------------------------------
// StackDevConv, factorized + dst-sorted edges + tf32 mma + prefetch pipeline.
//   W1 = [Wa | Wb];  A[n] = x[n]@(Wa-Wb)^T + b1 ;  B[n] = x[n]@Wb^T   (fp32)
//   per edge: h = ReLU(A[dst]+B[src]);  msg = h @ W2^T + b2           (tf32 mma)
//   out[n] = segment_max(msg, dst) ; empty -> 0
// Edge kernel double-buffers the gather in registers: next tile's random
// B[src] LDGs issue before this tile's mma (latency hidden under tensor work);
// A[dst] (L1-resident, sorted) + cvt land after mma. 2 syncs/tile.
// ----------------------------------------------------------------------------

#define DIMV    64
#define TPB     256
#define PADW    68
#define E_TILE  128
#define MAX_NODES 50000
#define MAX_EDGES 800000

#define SH 68    // sH  stride (uint32 tf32)
#define SW 72    // sW2 stride (uint32 tf32)  -> B-frag LDS conflict-free
#define SMS 68   // sMsg stride (float)

__device__ float g_h1[MAX_NODES * DIMV];
__device__ float g_A [MAX_NODES * DIMV];
__device__ float g_B [MAX_NODES * DIMV];
__device__ int   g_count [MAX_NODES];
__device__ int   g_offset[MAX_NODES];
__device__ int   g_src_s[MAX_EDGES];
__device__ int   g_dst_s[MAX_EDGES];

#define PRE_SMEM_FLOATS (64*PADW*3 + 64)
#define PRE_SMEM_BYTES  (PRE_SMEM_FLOATS*4)

#define EDGE_SMEM_WORDS (64*SW + 64 + 128*SH + 128*SMS + 128)
#define EDGE_SMEM_BYTES (EDGE_SMEM_WORDS*4)

__device__ __forceinline__ void atomic_max_float(float* addr, float value) {
    unsigned int ui = __float_as_uint(value);
    if ((int)ui >= 0) atomicMax((int*)addr, (int)ui);
    else              atomicMin((unsigned int*)addr, ui);
}

__device__ __forceinline__ unsigned int f2tf(float x) {
    unsigned int r;
    asm("cvt.rna.tf32.f32 %0, %1;" : "=r"(r) : "f"(x));
    return r;
}

__global__ void init_neg_inf_kernel(float* p, int n) {
    int i = blockIdx.x * blockDim.x + threadIdx.x;
    if (i < n) ((unsigned int*)p)[i] = 0xFF800000u;
}

__global__ void finalize_kernel(float* p, int n) {
    int i = blockIdx.x * blockDim.x + threadIdx.x;
    if (i < n) { float v = p[i]; if (!isfinite(v)) p[i] = 0.0f; }
}

// ---------------- counting sort by dst ----------------
__global__ void zero_count_kernel(int n_nodes) {
    int i = blockIdx.x * blockDim.x + threadIdx.x;
    if (i < n_nodes) g_count[i] = 0;
}

__global__ void hist_kernel(const int* __restrict__ dst, int n_edges) {
    int i = blockIdx.x * blockDim.x + threadIdx.x;
    if (i < n_edges) atomicAdd(&g_count[dst[i]], 1);
}

__global__ void scan_kernel(int n_nodes) {
    __shared__ int partial[1024];
    const int tid = threadIdx.x;
    const int chunk = (n_nodes + 1023) / 1024;
    const int begin = tid * chunk;
    const int end   = min(begin + chunk, n_nodes);
    int s = 0;
    for (int i = begin; i < end; i++) s += g_count[i];
    partial[tid] = s;
    __syncthreads();
    for (int off = 1; off < 1024; off <<= 1) {
        int v = partial[tid];
        int add = (tid >= off) ? partial[tid - off] : 0;
        __syncthreads();
        partial[tid] = v + add;
        __syncthreads();
    }
    int base = (tid > 0) ? partial[tid - 1] : 0;
    for (int i = begin; i < end; i++) { g_offset[i] = base; base += g_count[i]; }
}

__global__ void scatter_kernel(const int* __restrict__ src,
                               const int* __restrict__ dst, int n_edges) {
    int i = blockIdx.x * blockDim.x + threadIdx.x;
    if (i < n_edges) {
        int d = dst[i];
        int pos = atomicAdd(&g_offset[d], 1);
        g_src_s[pos] = src[i];
        g_dst_s[pos] = d;
    }
}

// ---------------- per-node precompute (fp32, exact) ----------------
__global__ __launch_bounds__(TPB, 3)
void pre_kernel(const float* __restrict__ x,
                const float* __restrict__ W1, const float* __restrict__ b1,
                float* __restrict__ A, float* __restrict__ B,
                int n_nodes, int finite_fix)
{
    extern __shared__ float smem[];
    float* sWdT = smem;
    float* sWbT = sWdT + 64 * PADW;
    float* sB1  = sWbT + 64 * PADW;
    float* sXT  = sB1 + 64;

    const int tid = threadIdx.x;

    for (int i = tid; i < 64 * 64; i += TPB) {
        int c = i >> 6, k = i & 63;
        float wa = W1[c * 128 + k];
        float wb = W1[c * 128 + 64 + k];
        sWdT[k * PADW + c] = wa - wb;
        sWbT[k * PADW + c] = wb;
    }
    if (tid < 64) sB1[tid] = b1[tid];

    const int n0 = blockIdx.x * 64;
    {
        const int e = tid >> 2;
        const int q = tid & 3;
        const int node = n0 + e;
        const float4* xr = (const float4*)(x + (size_t)(node < n_nodes ? node : 0) * DIMV);
        #pragma unroll
        for (int v = 0; v < 4; v++) {
            const int c4 = q * 4 + v;
            float4 a = (node < n_nodes) ? xr[c4] : make_float4(0.f,0.f,0.f,0.f);
            if (finite_fix) {
                if (!isfinite(a.x)) a.x = 0.f;
                if (!isfinite(a.y)) a.y = 0.f;
                if (!isfinite(a.z)) a.z = 0.f;
                if (!isfinite(a.w)) a.w = 0.f;
            }
            const int c = c4 * 4;
            sXT[(c + 0) * PADW + e] = a.x;
            sXT[(c + 1) * PADW + e] = a.y;
            sXT[(c + 2) * PADW + e] = a.z;
            sXT[(c + 3) * PADW + e] = a.w;
        }
    }
    __syncthreads();

    const int ty = tid >> 4, tx = tid & 15;
    const int r = ty * 4, cc = tx * 4;

    float accA[4][4], accB[4][4];
    #pragma unroll
    for (int i = 0; i < 4; i++)
        #pragma unroll
        for (int j = 0; j < 4; j++) { accA[i][j] = sB1[cc + j]; accB[i][j] = 0.f; }

    #pragma unroll 2
    for (int k = 0; k < 64; k++) {
        const float4 xf = *(const float4*)&sXT[k * PADW + r];
        const float4 wd = *(const float4*)&sWdT[k * PADW + cc];
        const float4 wb = *(const float4*)&sWbT[k * PADW + cc];
        const float a0 = xf.x, a1 = xf.y, a2 = xf.z, a3 = xf.w;
        accA[0][0]+=a0*wd.x; accA[0][1]+=a0*wd.y; accA[0][2]+=a0*wd.z; accA[0][3]+=a0*wd.w;
        accA[1][0]+=a1*wd.x; accA[1][1]+=a1*wd.y; accA[1][2]+=a1*wd.z; accA[1][3]+=a1*wd.w;
        accA[2][0]+=a2*wd.x; accA[2][1]+=a2*wd.y; accA[2][2]+=a2*wd.z; accA[2][3]+=a2*wd.w;
        accA[3][0]+=a3*wd.x; accA[3][1]+=a3*wd.y; accA[3][2]+=a3*wd.z; accA[3][3]+=a3*wd.w;
        accB[0][0]+=a0*wb.x; accB[0][1]+=a0*wb.y; accB[0][2]+=a0*wb.z; accB[0][3]+=a0*wb.w;
        accB[1][0]+=a1*wb.x; accB[1][1]+=a1*wb.y; accB[1][2]+=a1*wb.z; accB[1][3]+=a1*wb.w;
        accB[2][0]+=a2*wb.x; accB[2][1]+=a2*wb.y; accB[2][2]+=a2*wb.z; accB[2][3]+=a2*wb.w;
        accB[3][0]+=a3*wb.x; accB[3][1]+=a3*wb.y; accB[3][2]+=a3*wb.z; accB[3][3]+=a3*wb.w;
    }

    #pragma unroll
    for (int i = 0; i < 4; i++) {
        const int node = n0 + r + i;
        if (node < n_nodes) {
            *(float4*)&A[(size_t)node * DIMV + cc] =
                make_float4(accA[i][0], accA[i][1], accA[i][2], accA[i][3]);
            *(float4*)&B[(size_t)node * DIMV + cc] =
                make_float4(accB[i][0], accB[i][1], accB[i][2], accB[i][3]);
        }
    }
}

// ---------------- edge kernel: pipelined tf32 mma + run-merged scatter ----
__global__ __launch_bounds__(TPB, 2)
void edge_kernel(const float* __restrict__ A, const float* __restrict__ B,
                 const float* __restrict__ W2, const float* __restrict__ b2,
                 float* __restrict__ out, int n_edges)
{
    extern __shared__ unsigned int usmem[];
    unsigned int* sW2tf = usmem;                       // [k][n] tf32, stride SW
    float*        sB2   = (float*)(sW2tf + 64 * SW);
    unsigned int* sH    = (unsigned int*)(sB2 + 64);   // [e][k] tf32, stride SH
    float*        sMsg  = (float*)(sH + 128 * SH);     // [e][n], stride SMS
    int*          sDst  = (int*)(sMsg + 128 * SMS);

    const int tid  = threadIdx.x;
    const int wid  = tid >> 5;
    const int lane = tid & 31;
    const int grp  = lane >> 2;
    const int qd   = lane & 3;

    for (int i = tid; i < 64 * 64; i += TPB) {
        int n = i >> 6, k = i & 63;
        sW2tf[k * SW + n] = f2tf(W2[n * 64 + k]);
    }
    if (tid < 64) sB2[tid] = b2[tid];
    __syncthreads();

    const int ty = tid >> 4, tx = tid & 15;
    const int r = ty * 8, cc = tx * 4;
    const int e = tid >> 1, q = tid & 1;        // gather role: 2 threads/edge

    const int n_tiles = (n_edges + E_TILE - 1) / E_TILE;

    // ---- prologue: full prefetch of first tile into h regs ----
    uint4 h[8]; int dreg;
    {
        const int tile = blockIdx.x;
        const int eg = tile * E_TILE + e;
        const bool valid = (tile < n_tiles) && (eg < n_edges);
        int s = 0, d = -1;
        if (valid) { s = g_src_s[eg]; d = g_dst_s[eg]; }
        dreg = d;
        const float4* a4 = (const float4*)(A + (size_t)(valid ? d : 0) * DIMV) + q * 8;
        const float4* b4 = (const float4*)(B + (size_t)s * DIMV) + q * 8;
        #pragma unroll
        for (int v = 0; v < 8; v++) {
            float4 a = valid ? a4[v] : make_float4(0.f,0.f,0.f,0.f);
            float4 b = valid ? b4[v] : make_float4(0.f,0.f,0.f,0.f);
            h[v].x = f2tf(fmaxf(a.x + b.x, 0.f));
            h[v].y = f2tf(fmaxf(a.y + b.y, 0.f));
            h[v].z = f2tf(fmaxf(a.z + b.z, 0.f));
            h[v].w = f2tf(fmaxf(a.w + b.w, 0.f));
        }
    }

    for (int tile = blockIdx.x; tile < n_tiles; tile += gridDim.x) {
        // ---- commit h regs for this tile (STS.128) ----
        {
            uint4* hp = (uint4*)&sH[e * SH] + q * 8;
            #pragma unroll
            for (int v = 0; v < 8; v++) hp[v] = h[v];
            if (q == 0) sDst[e] = dreg;
        }
        __syncthreads();   // sync1: sH/sDst(t) visible

        // ---- issue next tile's random B[src] loads (latency hides under mma) ----
        const int ntile = tile + gridDim.x;
        const int egN = ntile * E_TILE + e;
        const bool validN = (ntile < n_tiles) && (egN < n_edges);
        int sN = 0, dN = -1;
        if (validN) { sN = g_src_s[egN]; dN = g_dst_s[egN]; }
        const float4* b4N = (const float4*)(B + (size_t)sN * DIMV) + q * 8;
        float4 bb[8];
        #pragma unroll
        for (int v = 0; v < 8; v++)
            bb[v] = validN ? b4N[v] : make_float4(0.f,0.f,0.f,0.f);

        // ---- tf32 mma on tile t ----
        {
            const int m0 = wid * 16;
            unsigned int af[8][4];
            #pragma unroll
            for (int ks = 0; ks < 8; ks++) {
                const int k0 = ks * 8;
                af[ks][0] = sH[(m0 + grp    ) * SH + k0 + qd    ];
                af[ks][1] = sH[(m0 + grp + 8) * SH + k0 + qd    ];
                af[ks][2] = sH[(m0 + grp    ) * SH + k0 + qd + 4];
                af[ks][3] = sH[(m0 + grp + 8) * SH + k0 + qd + 4];
            }
            #pragma unroll
            for (int nt = 0; nt < 8; nt++) {
                const int n0 = nt * 8;
                float c0 = 0.f, c1 = 0.f, c2 = 0.f, c3 = 0.f;
                #pragma unroll
                for (int ks = 0; ks < 8; ks++) {
                    const int k0 = ks * 8;
                    unsigned int b0 = sW2tf[(k0 + qd    ) * SW + n0 + grp];
                    unsigned int b1 = sW2tf[(k0 + qd + 4) * SW + n0 + grp];
                    asm volatile(
                        "mma.sync.aligned.m16n8k8.row.col.f32.tf32.tf32.f32 "
                        "{%0,%1,%2,%3}, {%4,%5,%6,%7}, {%8,%9}, {%0,%1,%2,%3};"
                        : "+f"(c0), "+f"(c1), "+f"(c2), "+f"(c3)
                        : "r"(af[ks][0]), "r"(af[ks][1]), "r"(af[ks][2]), "r"(af[ks][3]),
                          "r"(b0), "r"(b1));
                }
                const int col = n0 + 2 * qd;
                const float bb0 = sB2[col], bb1 = sB2[col + 1];
                float2 v0 = make_float2(c0 + bb0, c1 + bb1);
                float2 v1 = make_float2(c2 + bb0, c3 + bb1);
                *(float2*)&sMsg[(m0 + grp    ) * SMS + col] = v0;
                *(float2*)&sMsg[(m0 + grp + 8) * SMS + col] = v1;
            }
        }

        // ---- pre-read dst chain for scatter (sDst stable until next top) ----
        int rd[8];
        #pragma unroll
        for (int i = 0; i < 8; i++) rd[i] = sDst[r + i];

        // ---- finish next-tile prefetch: L1-resident A[dst] + fuse ----
        {
            const float4* a4N = (const float4*)(A + (size_t)(validN ? dN : 0) * DIMV) + q * 8;
            dreg = dN;
            #pragma unroll
            for (int v = 0; v < 8; v++) {
                float4 a = validN ? a4N[v] : make_float4(0.f,0.f,0.f,0.f);
                h[v].x = f2tf(fmaxf(a.x + bb[v].x, 0.f));
                h[v].y = f2tf(fmaxf(a.y + bb[v].y, 0.f));
                h[v].z = f2tf(fmaxf(a.z + bb[v].z, 0.f));
                h[v].w = f2tf(fmaxf(a.w + bb[v].w, 0.f));
            }
        }
        __syncthreads();   // sync2: sMsg(t) visible; sH consumers done

        // ---- scatter: run-merge within 8-edge chains, atomics at run ends ----
        {
            float4 cur = *(const float4*)&sMsg[r * SMS + cc];
            #pragma unroll
            for (int i = 0; i < 8; i++) {
                const int de = rd[i];
                const bool last = (i == 7) || (rd[i + 1] != de);
                if (!last) {
                    const float4 nx = *(const float4*)&sMsg[(r + i + 1) * SMS + cc];
                    cur.x = fmaxf(cur.x, nx.x);
                    cur.y = fmaxf(cur.y, nx.y);
                    cur.z = fmaxf(cur.z, nx.z);
                    cur.w = fmaxf(cur.w, nx.w);
                } else {
                    if (de >= 0) {
                        float* op = out + (size_t)de * DIMV + cc;
                        atomic_max_float(op + 0, cur.x);
                        atomic_max_float(op + 1, cur.y);
                        atomic_max_float(op + 2, cur.z);
                        atomic_max_float(op + 3, cur.w);
                    }
                    if (i < 7)
                        cur = *(const float4*)&sMsg[(r + i + 1) * SMS + cc];
                }
            }
        }
        // no sync: next loop-top writes sH/sDst (not read after sync2);
        // sMsg(t+1) writes are fenced by next sync1.
    }
}

extern "C" void kernel_launch(void* const* d_in, const int* in_sizes, int n_in,
                              void* d_out, int out_size)
{
    const float* x   = (const float*)d_in[0];
    const int*   ei  = (const int*)d_in[1];
    const float* W1a = (const float*)d_in[2];
    const float* b1a = (const float*)d_in[3];
    const float* W2a = (const float*)d_in[4];
    const float* b2a = (const float*)d_in[5];
    const float* W1b = (const float*)d_in[6];
    const float* b1b = (const float*)d_in[7];
    const float* W2b = (const float*)d_in[8];
    const float* b2b = (const float*)d_in[9];

    const int n_nodes = in_sizes[0] / DIMV;
    const int n_edges = in_sizes[1] / 2;
    const int* src = ei;
    const int* dst = ei + n_edges;

    float* out = (float*)d_out;
    float *h1, *Abuf, *Bbuf;
    cudaGetSymbolAddress((void**)&h1,   g_h1);
    cudaGetSymbolAddress((void**)&Abuf, g_A);
    cudaGetSymbolAddress((void**)&Bbuf, g_B);

    cudaFuncSetAttribute(pre_kernel,
                         cudaFuncAttributeMaxDynamicSharedMemorySize, PRE_SMEM_BYTES);
    cudaFuncSetAttribute(edge_kernel,
                         cudaFuncAttributeMaxDynamicSharedMemorySize, EDGE_SMEM_BYTES);

    const int n_feat = n_nodes * DIMV;
    const int init_blocks = (n_feat + TPB - 1) / TPB;
    const int pre_blocks  = (n_nodes + 63) / 64;
    const int edge_blocks = 148 * 2;
    const int eb = (n_edges + TPB - 1) / TPB;
    const int nb = (n_nodes + TPB - 1) / TPB;

    // ---- counting sort by dst (once; reused by both layers) ----
    zero_count_kernel<<<nb, TPB>>>(n_nodes);
    hist_kernel<<<eb, TPB>>>(dst, n_edges);
    scan_kernel<<<1, 1024>>>(n_nodes);
    scatter_kernel<<<eb, TPB>>>(src, dst, n_edges);

    // ---- layer 1 ----
    pre_kernel<<<pre_blocks, TPB, PRE_SMEM_BYTES>>>(x, W1a, b1a, Abuf, Bbuf, n_nodes, 0);
    init_neg_inf_kernel<<<init_blocks, TPB>>>(h1, n_feat);
    edge_kernel<<<edge_blocks, TPB, EDGE_SMEM_BYTES>>>(Abuf, Bbuf, W2a, b2a, h1, n_edges);

    // ---- layer 2 (h1 finalize fused via finite_fix) ----
    pre_kernel<<<pre_blocks, TPB, PRE_SMEM_BYTES>>>(h1, W1b, b1b, Abuf, Bbuf, n_nodes, 1);
    init_neg_inf_kernel<<<init_blocks, TPB>>>(out, n_feat);
    edge_kernel<<<edge_blocks, TPB, EDGE_SMEM_BYTES>>>(Abuf, Bbuf, W2b, b2b, out, n_edges);
    finalize_kernel<<<init_blocks, TPB>>>(out, n_feat);
}